// round 11
// baseline (speedup 1.0000x reference)
#include <cuda_runtime.h>
#include <cuda_fp16.h>
#include <cstdint>

#define T_TREES 100
#define NN      31
#define D       256
#define BATCH   8192
#define NU      16
#define NLEAF   32
#define NC      64

#define TPAD    112               // padded tree count (7 tiles x 16 trees)
#define AROWS   (TPAD * 16)       // 1792 rows in g_A (16 nodes per tree kept)
#define KA      256               // single fp16 term
#define TAU     0.05f

// ---------------- static scratch ----------------
__device__ __align__(256) __half g_A[AROWS * KA];     // 0.92 MB  Whi (all 16 nodes)
__device__ __align__(256) __half g_B[BATCH * D];      // 4.2 MB   Xhi
__device__ uint8_t g_leaf[T_TREES * BATCH];           // 800 KB

// ---------------- helpers ----------------
__device__ __forceinline__ uint32_t smem_u32(const void* p) {
    uint32_t a;
    asm("{ .reg .u64 t; cvta.to.shared.u64 t, %1; cvt.u32.u64 %0, t; }"
        : "=r"(a) : "l"(p));
    return a;
}
__device__ __forceinline__ void cp16(uint32_t dst, const void* src) {
    asm volatile("cp.async.cg.shared.global [%0], [%1], 16;\n" :: "r"(dst), "l"(src));
}
__device__ __forceinline__ void cp_commit() { asm volatile("cp.async.commit_group;\n"); }
template <int N> __device__ __forceinline__ void cp_wait() {
    asm volatile("cp.async.wait_group %0;\n" :: "n"(N));
}
__device__ __forceinline__ void ldsm4(uint32_t* r, uint32_t addr) {
    asm volatile("ldmatrix.sync.aligned.m8n8.x4.shared.b16 {%0,%1,%2,%3}, [%4];"
        : "=r"(r[0]), "=r"(r[1]), "=r"(r[2]), "=r"(r[3]) : "r"(addr));
}
__device__ __forceinline__ void mma16816(float* d, const uint32_t* a, const uint32_t* b) {
    asm volatile(
        "mma.sync.aligned.m16n8k16.row.col.f32.f16.f16.f32 "
        "{%0,%1,%2,%3}, {%4,%5,%6,%7}, {%8,%9}, {%0,%1,%2,%3};"
        : "+f"(d[0]), "+f"(d[1]), "+f"(d[2]), "+f"(d[3])
        : "r"(a[0]), "r"(a[1]), "r"(a[2]), "r"(a[3]), "r"(b[0]), "r"(b[1]));
}

// exact fp32 dot for the rare fix-up band (matches previously-validated routine)
__device__ __noinline__ float exact_dot(const float* __restrict__ node_w,
                                        const float* __restrict__ x,
                                        int tree, int node, int sample) {
    const float4* wp = (const float4*)(node_w + (size_t)(tree * NN + node) * D);
    const float4* xp = (const float4*)(x + (size_t)sample * D);
    float a0 = 0.f, a1 = 0.f, a2 = 0.f, a3 = 0.f;
    for (int i = 0; i < D / 4; i++) {
        float4 wv = wp[i], xv = xp[i];
        a0 += wv.x * xv.x; a1 += wv.y * xv.y;
        a2 += wv.z * xv.z; a3 += wv.w * xv.w;
    }
    return (a0 + a1) + (a2 + a3);
}

// ---------------- merged pack kernel ----------------
#define PACKW_BLKS (AROWS / 4)            // 448
#define PACKX_BLKS (BATCH * D / 1024)     // 2048
__global__ void k_pack(const float* __restrict__ node_w, const float* __restrict__ x) {
    if (blockIdx.x < PACKW_BLKS) {
        int row = blockIdx.x * 4 + (threadIdx.x >> 6);   // 0..1791
        int k = (threadIdx.x & 63) * 4;
        int tree = row >> 4, node = row & 15;
        __half hi[4];
        if (tree < T_TREES) {
            float4 w = *(const float4*)(node_w + (size_t)(tree * NN + node) * D + k);
            hi[0] = __float2half_rn(w.x); hi[1] = __float2half_rn(w.y);
            hi[2] = __float2half_rn(w.z); hi[3] = __float2half_rn(w.w);
        } else {
            hi[0] = hi[1] = hi[2] = hi[3] = __float2half_rn(0.f);
        }
        ((ushort4*)(g_A + (size_t)row * KA))[k / 4] = *(ushort4*)hi;
    } else {
        int i = ((blockIdx.x - PACKW_BLKS) * 256 + threadIdx.x) * 4;
        float4 w = *(const float4*)(x + i);
        __half h[4] = {__float2half_rn(w.x), __float2half_rn(w.y),
                       __float2half_rn(w.z), __float2half_rn(w.w)};
        *(ushort4*)(g_B + i) = *(ushort4*)h;
    }
}

// ---------------- Phase-1 GEMM (nodes 0..7) + traversal + phase-2 dots --------
#define GM 128                             // 16 trees x 8 nodes
#define GN 128
#define GK 64
#define TPC 16                             // trees per CTA
#define MTILES 7                           // 7 x 16 = 112 trees
#define NSTAGE 2
#define NCH (KA / GK)                      // 4
#define STRA 72                            // padded smem row (halfs) = 144 B

#define A_BYTES (GM * STRA * 2)            // 18432
#define STAGE_BYTES (2 * A_BYTES)          // 36864
#define OFF_SC   0
#define SC_LD    132
#define OFF_BIAS (NSTAGE * STAGE_BYTES)    // 73728  (256 floats = 1024 B)
#define OFF_WL   (OFF_BIAS + 1024)         // 74752  (2048 x u32 = 8192 B)
#define OFF_CNT  (OFF_WL + 8192)           // 82944
#define SMEM_TOTAL (OFF_CNT + 64)          // 83008 -> 2 CTA/SM

__global__ __launch_bounds__(256, 2)
void k_forest(const float* __restrict__ node_w, const float* __restrict__ node_b,
              const float* __restrict__ x) {
    extern __shared__ char sm[];
    const uint32_t sbase = smem_u32(sm);
    const int tid  = threadIdx.x;
    const int wid  = tid >> 5;
    const int lane = tid & 31;
    const int n0 = blockIdx.y * GN;
    const int T0 = blockIdx.x * TPC;       // first tree (16 per tile)

    float* sc = (float*)(sm + OFF_SC);
    float* sb = (float*)(sm + OFF_BIAS);          // 16 trees x 16 nodes
    uint32_t* wl = (uint32_t*)(sm + OFF_WL);
    int* wcnt = (int*)(sm + OFF_CNT);

    {   // biases: all 16 nodes (phase 2 needs 8..15)
        int tree = T0 + (tid >> 4);
        sb[tid] = (tree < T_TREES) ? node_b[tree * NN + (tid & 15)] : 0.f;
        if (tid == 0) *wcnt = 0;
    }

    auto load_chunk = [&](int c, int stg) {
        const uint32_t sA = sbase + stg * STAGE_BYTES;
        const uint32_t sB = sA + A_BYTES;
        const int k0 = c * GK;
#pragma unroll
        for (int r = 0; r < 4; r++) {      // A: 128 rows (tree*16 + node0..7)
            int op = tid + 256 * r;
            int row = op >> 3, q = op & 7;
            int grow = (T0 + (row >> 3)) * 16 + (row & 7);
            cp16(sA + (uint32_t)(row * STRA + q * 8) * 2,
                 g_A + (size_t)grow * KA + k0 + q * 8);
        }
#pragma unroll
        for (int r = 0; r < 4; r++) {      // B: 128 rows x 8 x 16B
            int op = tid + 256 * r;
            int row = op >> 3, q = op & 7;
            cp16(sB + (uint32_t)(row * STRA + q * 8) * 2,
                 g_B + (size_t)(n0 + row) * D + k0 + q * 8);
        }
        cp_commit();
    };

    load_chunk(0, 0); load_chunk(1, 1);

    // warp tiling: 2 (M) x 4 (N) warps, warp tile 64x32
    const int m0w = (wid & 1) * 64;
    const int n0w = (wid >> 1) * 32;
    const int aBase = (m0w + (lane & 15)) * STRA + (lane >> 4) * 8;
    const int bBase = (n0w + (lane & 7) + ((lane >> 4) << 3)) * STRA
                      + ((lane >> 3) & 1) * 8;

    float acc[4][4][4];
#pragma unroll
    for (int i = 0; i < 4; i++)
#pragma unroll
        for (int j = 0; j < 4; j++)
#pragma unroll
            for (int q = 0; q < 4; q++) acc[i][j][q] = 0.f;

    for (int c = 0; c < NCH; c++) {
        const int stg = c % NSTAGE;
        cp_wait<NSTAGE - 1>();
        __syncthreads();
        const uint32_t sA = sbase + stg * STAGE_BYTES;
        const uint32_t sB = sA + A_BYTES;

        uint32_t af[2][4][4], bf[2][2][4];
#pragma unroll
        for (int j = 0; j < 2; j++)
            ldsm4(bf[0][j], sB + (uint32_t)(bBase + j * 16 * STRA) * 2);
#pragma unroll
        for (int mt = 0; mt < 4; mt++)
            ldsm4(af[0][mt], sA + (uint32_t)(aBase + mt * 16 * STRA) * 2);

#pragma unroll
        for (int s = 0; s < 4; s++) {
            const int kk = s * 16;
            const int cur = s & 1, nxt = cur ^ 1;
            if (s < 3) {
#pragma unroll
                for (int j = 0; j < 2; j++)
                    ldsm4(bf[nxt][j],
                          sB + (uint32_t)(bBase + j * 16 * STRA + kk + 16) * 2);
#pragma unroll
                for (int mt = 0; mt < 4; mt++)
                    ldsm4(af[nxt][mt],
                          sA + (uint32_t)(aBase + mt * 16 * STRA + kk + 16) * 2);
            }
#pragma unroll
            for (int mt = 0; mt < 4; mt++)
#pragma unroll
                for (int nt = 0; nt < 4; nt++)
                    mma16816(acc[mt][nt], af[cur][mt], &bf[cur][nt >> 1][(nt & 1) * 2]);
        }
        __syncthreads();
        if (c + NSTAGE < NCH) load_chunk(c + NSTAGE, stg);
        else cp_commit();
    }

    // ---- scores to smem ----
#pragma unroll
    for (int mt = 0; mt < 4; mt++) {
        int row = m0w + mt * 16 + (lane >> 2);
#pragma unroll
        for (int nt = 0; nt < 4; nt++) {
            int nloc = n0w + nt * 8 + (lane & 3) * 2;
            *(float2*)(sc + row * SC_LD + nloc) =
                make_float2(acc[mt][nt][0], acc[mt][nt][1]);
            *(float2*)(sc + (row + 8) * SC_LD + nloc) =
                make_float2(acc[mt][nt][2], acc[mt][nt][3]);
        }
    }
    __syncthreads();

    // ---- traversal: 4 levels from smem (nodes 0..7), push idx4>=8 to worklist
#pragma unroll
    for (int task = tid; task < TPC * GN; task += 256) {   // 2048 tasks
        int tt = task >> 7, s = task & 127;
        int tree = T0 + tt;
        if (tree < T_TREES) {
            int sample = n0 + s;
            int idx = 0;
#pragma unroll
            for (int l = 0; l < 4; l++) {
                float z = sc[(tt * 8 + idx) * SC_LD + s] + sb[tt * 16 + idx];
                if (fabsf(z) < TAU)
                    z = exact_dot(node_w, x, tree, idx, sample) + sb[tt * 16 + idx];
                idx = 2 * idx + (z <= 0.0f ? 1 : 0);
            }
            if (idx < 8) {        // level-4 node already in phase-1 scores
                float z = sc[(tt * 8 + idx) * SC_LD + s] + sb[tt * 16 + idx];
                if (fabsf(z) < TAU)
                    z = exact_dot(node_w, x, tree, idx, sample) + sb[tt * 16 + idx];
                g_leaf[(size_t)tree * BATCH + sample] =
                    (uint8_t)(2 * idx + (z <= 0.0f ? 1 : 0));
            } else {              // defer to phase-2 warp dots
                int slot = atomicAdd(wcnt, 1);
                wl[slot] = ((uint32_t)task << 4) | (uint32_t)idx;
            }
        }
    }
    __syncthreads();

    // ---- phase 2: warp-cooperative fp16 dots for nodes 8..15 ----
    const int cnt = *wcnt;
#pragma unroll 2
    for (int e = wid; e < cnt; e += 8) {
        uint32_t ent = wl[e];
        int idx4 = ent & 15;
        int task = ent >> 4;
        int tt = task >> 7, s = task & 127;
        int tree = T0 + tt;
        int sample = n0 + s;
        const uint4 wv = *(const uint4*)(g_A + (size_t)(tree * 16 + idx4) * KA + lane * 8);
        const uint4 xv = *(const uint4*)(g_B + (size_t)sample * D + lane * 8);
        const __half2* wh = (const __half2*)&wv;
        const __half2* xh = (const __half2*)&xv;
        float a = 0.f;
#pragma unroll
        for (int j = 0; j < 4; j++) {
            float2 wf = __half22float2(wh[j]);
            float2 xf = __half22float2(xh[j]);
            a += wf.x * xf.x + wf.y * xf.y;
        }
#pragma unroll
        for (int off = 16; off >= 1; off >>= 1)
            a += __shfl_xor_sync(0xffffffffu, a, off);
        if (lane == 0) {
            float z = a + sb[tt * 16 + idx4];
            if (fabsf(z) < TAU)
                z = exact_dot(node_w, x, tree, idx4, sample) + sb[tt * 16 + idx4];
            g_leaf[(size_t)tree * BATCH + sample] =
                (uint8_t)(2 * idx4 + (z <= 0.0f ? 1 : 0));
        }
    }
}

// ---------------- leaf gather + forest mean (R9 layout) ----------------
#define GSS 16
__global__ __launch_bounds__(256, 6)
void k_gather(const float* __restrict__ leaves, float* __restrict__ out) {
    __shared__ uint8_t sidx[T_TREES * GSS];       // 1600 B
    const int s0  = blockIdx.x * GSS;
    const int tid = threadIdx.x;

    for (int i = tid; i < T_TREES * GSS / 4; i += 256) {
        int t = i >> 2, w = i & 3;
        ((uint32_t*)sidx)[i] =
            *(const uint32_t*)(g_leaf + (size_t)t * BATCH + s0 + w * 4);
    }
    __syncthreads();

    const int s = tid >> 4;      // 16 samples
    const int q = tid & 15;      // 16 class-quads
    float4 a = make_float4(0.f, 0.f, 0.f, 0.f);

#pragma unroll 4
    for (int t = 0; t < T_TREES; t++) {
        int idx = sidx[t * GSS + s];
        float4 v = *(const float4*)(leaves +
            ((size_t)(t * NLEAF + idx)) * NC + q * 4);
        a.x += v.x; a.y += v.y; a.z += v.z; a.w += v.w;
    }
    const float scl = 1.0f / (float)T_TREES;
    *(float4*)(out + (size_t)(s0 + s) * NC + q * 4) =
        make_float4(a.x * scl, a.y * scl, a.z * scl, a.w * scl);
}

// ---------------- launch ----------------
extern "C" void kernel_launch(void* const* d_in, const int* in_sizes, int n_in,
                              void* d_out, int out_size) {
    const float* x      = (const float*)d_in[0];   // [8192,256]
    const float* node_w = (const float*)d_in[1];   // [100,31,256]
    const float* node_b = (const float*)d_in[2];   // [100,31]
    const float* leaves = (const float*)d_in[3];   // [100,32,64]
    float* out = (float*)d_out;                    // [8192,64]

    k_pack<<<PACKW_BLKS + PACKX_BLKS, 256>>>(node_w, x);

    cudaFuncSetAttribute(k_forest, cudaFuncAttributeMaxDynamicSharedMemorySize,
                         SMEM_TOTAL);
    k_forest<<<dim3(MTILES, BATCH / GN), 256, SMEM_TOTAL>>>(node_w, node_b, x);

    k_gather<<<BATCH / GSS, 256>>>(leaves, out);
}

// round 12
// speedup vs baseline: 2.0821x; 2.0821x over previous
#include <cuda_runtime.h>
#include <cuda_fp16.h>
#include <cstdint>

#define T_TREES 100
#define NN      31
#define D       256
#define BATCH   8192
#define NU      16
#define NLEAF   32
#define NC      64

#define MROWS   1664              // 13 * 128 (1600 used, rest zero)
#define KA      256               // single fp16 term
#define TAU     0.05f

// ---------------- static scratch ----------------
__device__ __align__(256) __half g_A[MROWS * KA];     // 0.85 MB  Whi
__device__ __align__(256) __half g_B[BATCH * D];      // 4.2 MB   Xhi
__device__ uint8_t g_leaf[T_TREES * BATCH];           // 800 KB

// ---------------- helpers ----------------
__device__ __forceinline__ uint32_t smem_u32(const void* p) {
    uint32_t a;
    asm("{ .reg .u64 t; cvta.to.shared.u64 t, %1; cvt.u32.u64 %0, t; }"
        : "=r"(a) : "l"(p));
    return a;
}
__device__ __forceinline__ void cp16(uint32_t dst, const void* src) {
    asm volatile("cp.async.cg.shared.global [%0], [%1], 16;\n" :: "r"(dst), "l"(src));
}
__device__ __forceinline__ void cp_commit() { asm volatile("cp.async.commit_group;\n"); }
template <int N> __device__ __forceinline__ void cp_wait() {
    asm volatile("cp.async.wait_group %0;\n" :: "n"(N));
}
__device__ __forceinline__ void ldsm4(uint32_t* r, uint32_t addr) {
    asm volatile("ldmatrix.sync.aligned.m8n8.x4.shared.b16 {%0,%1,%2,%3}, [%4];"
        : "=r"(r[0]), "=r"(r[1]), "=r"(r[2]), "=r"(r[3]) : "r"(addr));
}
__device__ __forceinline__ void mma16816(float* d, const uint32_t* a, const uint32_t* b) {
    asm volatile(
        "mma.sync.aligned.m16n8k16.row.col.f32.f16.f16.f32 "
        "{%0,%1,%2,%3}, {%4,%5,%6,%7}, {%8,%9}, {%0,%1,%2,%3};"
        : "+f"(d[0]), "+f"(d[1]), "+f"(d[2]), "+f"(d[3])
        : "r"(a[0]), "r"(a[1]), "r"(a[2]), "r"(a[3]), "r"(b[0]), "r"(b[1]));
}

// ---------------- merged pack kernel (MLP=4: 4 independent loads/thread) -----
// W part: 104 blocks x 16 rows each; thread handles 4 rows (stride-4), 1 quad
// X part: 512 blocks x 4096 elems; thread handles 4 x float4
#define PACKW_BLKS (MROWS / 16)           // 104
#define PACKX_BLKS (BATCH * D / 4096)     // 512
__global__ void k_pack(const float* __restrict__ node_w, const float* __restrict__ x) {
    const int tid = threadIdx.x;
    if (blockIdx.x < PACKW_BLKS) {
        const int k = (tid & 63) * 4;
        const int r0 = blockIdx.x * 16 + (tid >> 6);   // rows r0, r0+4, r0+8, r0+12
        float4 w[4];
#pragma unroll
        for (int j = 0; j < 4; j++) {                  // 4 independent loads
            int row = r0 + 4 * j;
            if (row < T_TREES * NU) {
                int g = (row >> 4) * NN + (row & 15);
                w[j] = *(const float4*)(node_w + (size_t)g * D + k);
            } else {
                w[j] = make_float4(0.f, 0.f, 0.f, 0.f);
            }
        }
#pragma unroll
        for (int j = 0; j < 4; j++) {
            int row = r0 + 4 * j;
            __half h[4] = {__float2half_rn(w[j].x), __float2half_rn(w[j].y),
                           __float2half_rn(w[j].z), __float2half_rn(w[j].w)};
            ((ushort4*)(g_A + (size_t)row * KA))[k / 4] = *(ushort4*)h;
        }
    } else {
        const int base = (blockIdx.x - PACKW_BLKS) * 4096 + tid * 4;
        float4 w[4];
#pragma unroll
        for (int j = 0; j < 4; j++)                    // 4 independent loads
            w[j] = *(const float4*)(x + base + j * 1024);
#pragma unroll
        for (int j = 0; j < 4; j++) {
            __half h[4] = {__float2half_rn(w[j].x), __float2half_rn(w[j].y),
                           __float2half_rn(w[j].z), __float2half_rn(w[j].w)};
            *(ushort4*)(g_B + base + j * 1024) = *(ushort4*)h;
        }
    }
}

// ---------------- GEMM (mma.sync fp16) + traversal  [R9 best config] ---------
#define GM 128
#define GN 128
#define GK 64                              // fp16 elems per chunk (128 B rows)
#define NSTAGE 2
#define NCH (KA / GK)                      // 4
#define STRA 72                            // padded smem row (halfs) = 144 B

#define A_BYTES (GM * STRA * 2)            // 18432
#define STAGE_BYTES (2 * A_BYTES)          // 36864 (A + B)
#define OFF_SC   0                         // scores span BOTH stages after mainloop
#define SC_LD    132                       // 128 sample cols + 4 pad
#define OFF_BIAS (NSTAGE * STAGE_BYTES)    // 73728
#define SMEM_TOTAL (OFF_BIAS + 512 + 64)   // 74304 -> 2 CTA/SM

__global__ __launch_bounds__(256, 2)
void k_forest(const float* __restrict__ node_w, const float* __restrict__ node_b,
              const float* __restrict__ x) {
    extern __shared__ char sm[];
    const uint32_t sbase = smem_u32(sm);
    const int tid  = threadIdx.x;
    const int wid  = tid >> 5;
    const int lane = tid & 31;
    const int m0 = blockIdx.x * GM;
    const int n0 = blockIdx.y * GN;
    const int T0 = m0 >> 4;                // first tree (8 per tile)

    float* sc = (float*)(sm + OFF_SC);
    float* sb = (float*)(sm + OFF_BIAS);

    if (tid < 128) {
        int tree = T0 + (tid >> 4);
        sb[tid] = (tree < T_TREES) ? node_b[tree * NN + (tid & 15)] : 0.f;
    }

    auto load_chunk = [&](int c, int stg) {
        const uint32_t sA = sbase + stg * STAGE_BYTES;
        const uint32_t sB = sA + A_BYTES;
        const int k0 = c * GK;
#pragma unroll
        for (int r = 0; r < 4; r++) {      // A: 128 rows x 8 x 16B
            int op = tid + 256 * r;
            int row = op >> 3, q = op & 7;
            cp16(sA + (uint32_t)(row * STRA + q * 8) * 2,
                 g_A + (size_t)(m0 + row) * KA + k0 + q * 8);
        }
#pragma unroll
        for (int r = 0; r < 4; r++) {      // B: 128 rows x 8 x 16B
            int op = tid + 256 * r;
            int row = op >> 3, q = op & 7;
            cp16(sB + (uint32_t)(row * STRA + q * 8) * 2,
                 g_B + (size_t)(n0 + row) * D + k0 + q * 8);
        }
        cp_commit();
    };

    load_chunk(0, 0); load_chunk(1, 1);

    // warp tiling: 2 (M) x 4 (N) warps, warp tile 64x32
    const int m0w = (wid & 1) * 64;
    const int n0w = (wid >> 1) * 32;
    const int aBase = (m0w + (lane & 15)) * STRA + (lane >> 4) * 8;
    const int bBase = (n0w + (lane & 7) + ((lane >> 4) << 3)) * STRA
                      + ((lane >> 3) & 1) * 8;

    float acc[4][4][4];
#pragma unroll
    for (int i = 0; i < 4; i++)
#pragma unroll
        for (int j = 0; j < 4; j++)
#pragma unroll
            for (int q = 0; q < 4; q++) acc[i][j][q] = 0.f;

    for (int c = 0; c < NCH; c++) {
        const int stg = c % NSTAGE;
        cp_wait<NSTAGE - 1>();
        __syncthreads();
        const uint32_t sA = sbase + stg * STAGE_BYTES;
        const uint32_t sB = sA + A_BYTES;

        // fully software-pipelined fragments: A AND B double-buffered
        uint32_t af[2][4][4], bf[2][2][4];
#pragma unroll
        for (int j = 0; j < 2; j++)
            ldsm4(bf[0][j], sB + (uint32_t)(bBase + j * 16 * STRA) * 2);
#pragma unroll
        for (int mt = 0; mt < 4; mt++)
            ldsm4(af[0][mt], sA + (uint32_t)(aBase + mt * 16 * STRA) * 2);

#pragma unroll
        for (int s = 0; s < 4; s++) {
            const int kk = s * 16;
            const int cur = s & 1, nxt = cur ^ 1;
            if (s < 3) {                    // prefetch next k-step (B first, then A)
#pragma unroll
                for (int j = 0; j < 2; j++)
                    ldsm4(bf[nxt][j],
                          sB + (uint32_t)(bBase + j * 16 * STRA + kk + 16) * 2);
#pragma unroll
                for (int mt = 0; mt < 4; mt++)
                    ldsm4(af[nxt][mt],
                          sA + (uint32_t)(aBase + mt * 16 * STRA + kk + 16) * 2);
            }
#pragma unroll
            for (int mt = 0; mt < 4; mt++)
#pragma unroll
                for (int nt = 0; nt < 4; nt++)
                    mma16816(acc[mt][nt], af[cur][mt], &bf[cur][nt >> 1][(nt & 1) * 2]);
        }
        __syncthreads();
        if (c + NSTAGE < NCH) load_chunk(c + NSTAGE, stg);
        else cp_commit();
    }

    // ---- epilogue: single pass, all 128 samples (scores span both stages) ----
#pragma unroll
    for (int mt = 0; mt < 4; mt++) {
        int row = m0w + mt * 16 + (lane >> 2);
#pragma unroll
        for (int nt = 0; nt < 4; nt++) {
            int nloc = n0w + nt * 8 + (lane & 3) * 2;
            *(float2*)(sc + row * SC_LD + nloc) =
                make_float2(acc[mt][nt][0], acc[mt][nt][1]);
            *(float2*)(sc + (row + 8) * SC_LD + nloc) =
                make_float2(acc[mt][nt][2], acc[mt][nt][3]);
        }
    }
    __syncthreads();

#pragma unroll
    for (int task = tid; task < 1024; task += 256) {
        int tt = task >> 7, s = task & 127;
        int tree = T0 + tt;
        if (tree < T_TREES) {
            int sample = n0 + s;
            int idx = 0;
#pragma unroll
            for (int l = 0; l < 5; l++) {
                int node = (tt << 4) + idx;
                float z = sc[node * SC_LD + s] + sb[node];
                if (fabsf(z) < TAU) {     // rare exact fp32 recompute
                    const float4* wp = (const float4*)(node_w +
                        (size_t)(tree * NN + idx) * D);
                    const float4* xp = (const float4*)(x + (size_t)sample * D);
                    float a0 = 0.f, a1 = 0.f, a2 = 0.f, a3 = 0.f;
                    for (int i = 0; i < D / 4; i++) {
                        float4 wv = wp[i], xv = xp[i];
                        a0 += wv.x * xv.x; a1 += wv.y * xv.y;
                        a2 += wv.z * xv.z; a3 += wv.w * xv.w;
                    }
                    z = ((a0 + a1) + (a2 + a3)) + sb[node];
                }
                idx = 2 * idx + (z <= 0.0f ? 1 : 0);
            }
            g_leaf[(size_t)tree * BATCH + sample] = (uint8_t)idx;
        }
    }
}

// ---------------- leaf gather + forest mean (R9 layout) ----------------
// CTA = 16 samples x ALL 64 classes; warp = 2 full 256B rows -> 4 full lines.
#define GSS 16
__global__ __launch_bounds__(256, 6)
void k_gather(const float* __restrict__ leaves, float* __restrict__ out) {
    __shared__ uint8_t sidx[T_TREES * GSS];       // 1600 B
    const int s0  = blockIdx.x * GSS;
    const int tid = threadIdx.x;

    for (int i = tid; i < T_TREES * GSS / 4; i += 256) {
        int t = i >> 2, w = i & 3;
        ((uint32_t*)sidx)[i] =
            *(const uint32_t*)(g_leaf + (size_t)t * BATCH + s0 + w * 4);
    }
    __syncthreads();

    const int s = tid >> 4;      // 16 samples
    const int q = tid & 15;      // 16 class-quads (full 64 classes)
    float4 a = make_float4(0.f, 0.f, 0.f, 0.f);

#pragma unroll 4
    for (int t = 0; t < T_TREES; t++) {
        int idx = sidx[t * GSS + s];
        float4 v = *(const float4*)(leaves +
            ((size_t)(t * NLEAF + idx)) * NC + q * 4);
        a.x += v.x; a.y += v.y; a.z += v.z; a.w += v.w;
    }
    const float scl = 1.0f / (float)T_TREES;
    *(float4*)(out + (size_t)(s0 + s) * NC + q * 4) =
        make_float4(a.x * scl, a.y * scl, a.z * scl, a.w * scl);
}

// ---------------- launch ----------------
extern "C" void kernel_launch(void* const* d_in, const int* in_sizes, int n_in,
                              void* d_out, int out_size) {
    const float* x      = (const float*)d_in[0];   // [8192,256]
    const float* node_w = (const float*)d_in[1];   // [100,31,256]
    const float* node_b = (const float*)d_in[2];   // [100,31]
    const float* leaves = (const float*)d_in[3];   // [100,32,64]
    float* out = (float*)d_out;                    // [8192,64]

    k_pack<<<PACKW_BLKS + PACKX_BLKS, 256>>>(node_w, x);

    cudaFuncSetAttribute(k_forest, cudaFuncAttributeMaxDynamicSharedMemorySize,
                         SMEM_TOTAL);
    k_forest<<<dim3(MROWS / GM, BATCH / GN), 256, SMEM_TOTAL>>>(node_w, node_b, x);

    k_gather<<<BATCH / GSS, 256>>>(leaves, out);
}